// round 5
// baseline (speedup 1.0000x reference)
#include <cuda_runtime.h>
#include <cuda_bf16.h>

// x[B=2048, C=16, S=2000] fp32.
// Attention branch is identity (softmax rows sum to 1), so:
//   out[b,j,s] = LN_j( sum_c Wp[j,c]*x[b,c,s] + bp[j] ) * gp[j] + hp[j]
//
// R4: float2 per thread (was float4) to cut regs 127 -> ~85 and raise
// occupancy from 2 to 3 CTAs/SM. Memory-bound; more warps => more MLP.

#define CN   16
#define SN   2000
#define BN   2048
#define LN_EPS 1e-5f

__global__ __launch_bounds__(256, 3) void fused_proj_ln2(
    const float* __restrict__ x,
    const float* __restrict__ Wp,
    const float* __restrict__ bp,
    const float* __restrict__ gp,
    const float* __restrict__ hp,
    float* __restrict__ out)
{
    __shared__ float sW[CN * CN];
    __shared__ float sb[CN], sg[CN], sh[CN];

    const int t = threadIdx.x;
    if (t < CN * CN) sW[t] = Wp[t];
    if (t < CN) { sb[t] = bp[t]; sg[t] = gp[t]; sh[t] = hp[t]; }
    __syncthreads();

    // One thread handles 2 consecutive s positions (float2). 1000 groups per b.
    const unsigned GPB = SN / 2;                  // 1000
    unsigned g = blockIdx.x * 256u + (unsigned)t;
    if (g >= (unsigned)BN * GPB) return;          // grid sized exactly; guard anyway
    const unsigned b  = g / GPB;
    const unsigned s2 = (g % GPB) * 2u;

    const float* xb = x + (size_t)b * (CN * SN) + s2;

    // 16 coalesced LDG.64 (warp: 256B contiguous per load), front-batched for MLP.
    float2 v[CN];
#pragma unroll
    for (int c = 0; c < CN; ++c)
        v[c] = *reinterpret_cast<const float2*>(xb + (size_t)c * SN);

    // y[j] = bp[j] + sum_c Wp[j,c] * v[c]
    float2 y[CN];
    float2 mu = make_float2(0.f, 0.f);
#pragma unroll
    for (int j = 0; j < CN; ++j) {
        const float bj = sb[j];
        float2 acc = make_float2(bj, bj);
#pragma unroll
        for (int c = 0; c < CN; ++c) {
            const float w = sW[j * CN + c];
            acc.x = fmaf(w, v[c].x, acc.x);
            acc.y = fmaf(w, v[c].y, acc.y);
        }
        y[j] = acc;
        mu.x += acc.x; mu.y += acc.y;
    }

    const float inv = 1.0f / (float)CN;
    mu.x *= inv; mu.y *= inv;

    float2 var = make_float2(0.f, 0.f);
#pragma unroll
    for (int j = 0; j < CN; ++j) {
        const float dx = y[j].x - mu.x;
        const float dy = y[j].y - mu.y;
        var.x = fmaf(dx, dx, var.x);
        var.y = fmaf(dy, dy, var.y);
    }
    float2 rs;
    rs.x = rsqrtf(var.x * inv + LN_EPS);
    rs.y = rsqrtf(var.y * inv + LN_EPS);

    float* ob = out + (size_t)b * (CN * SN) + s2;
#pragma unroll
    for (int j = 0; j < CN; ++j) {
        const float gj = sg[j];
        const float hj = sh[j];
        float2 o;
        o.x = fmaf((y[j].x - mu.x) * rs.x, gj, hj);
        o.y = fmaf((y[j].y - mu.y) * rs.y, gj, hj);
        *reinterpret_cast<float2*>(ob + (size_t)j * SN) = o;
    }
}

extern "C" void kernel_launch(void* const* d_in, const int* in_sizes, int n_in,
                              void* d_out, int out_size)
{
    // metadata order: x, Wq, bq, gq, hq, Wk, bk, gk, hk, Wp, bp, gp, hp
    const float* x  = (const float*)d_in[0];
    const float* Wp = (const float*)d_in[9];
    const float* bp = (const float*)d_in[10];
    const float* gp = (const float*)d_in[11];
    const float* hp = (const float*)d_in[12];
    float* out = (float*)d_out;

    const unsigned groups = (unsigned)BN * (SN / 2);   // 2,048,000
    const unsigned blocks = (groups + 255u) / 256u;    // 8000
    fused_proj_ln2<<<blocks, 256>>>(x, Wp, bp, gp, hp, out);
}